// round 9
// baseline (speedup 1.0000x reference)
#include <cuda_runtime.h>
#include <cstdint>

// Problem constants (fixed shapes)
#define PN    100000   // nodes
#define PE    100000   // hyperedges
#define PNNZ  800000   // edges (nnz)
#define PR    4        // ranks
#define PF    64       // features

#define NTILE 1024
#define NB_C  ((PE + NTILE - 1) / NTILE)   // 98
#define NB_R  ((PN + NTILE - 1) / NTILE)   // 98

// ---- scratch (__device__ globals; no allocation). ~47 MB total.
// RULE (hard-won in rounds 3-6): these symbols are referenced ONLY from
// device code; never passed as host-side kernel arguments (host shadow
// address = UB = 128 MB checkpoint violation).
__device__ int    g_is64;
__device__ int    g_alloc_c;            // region allocator for col bins
__device__ int    g_alloc_r;            // region allocator for row bins
__device__ int    g_cnt_c[PE];
__device__ int    g_cnt_r[PN];
__device__ int    g_ptr_c[PE];
__device__ int    g_ptr_r[PN];
__device__ int    g_cur_c[PE];
__device__ int    g_cur_r[PN];
__device__ __align__(16) float  g_he_feat[(size_t)PE * PF];   // 25.6 MB dense
__device__ __align__(8)  int2   g_e1[PNNZ];   // by col-bin: (row, val bits)      6.4 MB
__device__ __align__(16) float4 g_e2[PNNZ];   // by row-bin: (col bits, s0,s1,s2) 12.8 MB

__device__ __forceinline__ long long load_idx(const void* p, long long i, int is64) {
    if (is64) return ((const long long*)p)[i];
    return (long long)((const int*)p)[i];
}

// --- zero histograms + allocators + dtype sniff (every replay).
// int64 LE indices < 2^31 -> every odd 32-bit word is 0.
__global__ void zero_and_detect(const void* rows) {
    int t = blockIdx.x * blockDim.x + threadIdx.x;
    if (t == 0) {
        const int* p = (const int*)rows;
        int all0 = 1;
        #pragma unroll 4
        for (int i = 0; i < 1024; i++) {
            if (p[2 * i + 1] != 0) { all0 = 0; break; }
        }
        g_is64 = all0;
        g_alloc_c = 0;
        g_alloc_r = 0;
    }
    int total = PE + PN;
    for (; t < total; t += gridDim.x * blockDim.x) {
        if (t < PE) g_cnt_c[t] = 0;
        else        g_cnt_r[t - PE] = 0;
    }
}

// --- histogram edges by col and by row; 4 edges per thread (vectorized loads)
__global__ void histogram_edges(const void* __restrict__ rows,
                                const void* __restrict__ cols) {
    int is64 = g_is64;
    long long e0 = ((long long)blockIdx.x * blockDim.x + threadIdx.x) * 4;
    if (e0 >= PNNZ) return;
    int r[4], c[4];
    if (is64) {
        const longlong2* r2 = (const longlong2*)rows;
        const longlong2* c2 = (const longlong2*)cols;
        longlong2 ra = r2[e0 >> 1], rb = r2[(e0 >> 1) + 1];
        longlong2 ca = c2[e0 >> 1], cb = c2[(e0 >> 1) + 1];
        r[0] = (int)ra.x; r[1] = (int)ra.y; r[2] = (int)rb.x; r[3] = (int)rb.y;
        c[0] = (int)ca.x; c[1] = (int)ca.y; c[2] = (int)cb.x; c[3] = (int)cb.y;
    } else {
        int4 ra = ((const int4*)rows)[e0 >> 2];
        int4 ca = ((const int4*)cols)[e0 >> 2];
        r[0] = ra.x; r[1] = ra.y; r[2] = ra.z; r[3] = ra.w;
        c[0] = ca.x; c[1] = ca.y; c[2] = ca.z; c[3] = ca.w;
    }
    #pragma unroll
    for (int k = 0; k < 4; k++) {
        if (e0 + k < PNNZ) {
            atomicAdd(&g_cnt_c[c[k]], 1);
            atomicAdd(&g_cnt_r[r[k]], 1);
        }
    }
}

// --- single-kernel offset assignment: per-tile smem scan + atomic region grab.
// Bins need only DISJOINT contiguous regions, not index-ordered ones, so each
// tile claims its span with one atomicAdd. Gathers use ptr[] + cnt[] for ends.
__global__ void assign_offsets() {
    __shared__ int sm[NTILE];
    __shared__ int base_sh;
    int b = blockIdx.x;
    bool isC = (b < NB_C);
    const int* cnt = isC ? g_cnt_c : g_cnt_r;
    int*       ptr = isC ? g_ptr_c : g_ptr_r;
    int*       cur = isC ? g_cur_c : g_cur_r;
    int n    = isC ? PE : PN;
    int tile = isC ? b : b - NB_C;
    int t = threadIdx.x;
    int i = tile * NTILE + t;
    int v = (i < n) ? cnt[i] : 0;
    sm[t] = v;
    __syncthreads();
    #pragma unroll
    for (int d = 1; d < NTILE; d <<= 1) {
        int u = (t >= d) ? sm[t - d] : 0;
        __syncthreads();
        sm[t] += u;
        __syncthreads();
    }
    if (t == NTILE - 1)
        base_sh = atomicAdd(isC ? &g_alloc_c : &g_alloc_r, sm[t]);
    __syncthreads();
    if (i < n) {
        int p = base_sh + sm[t] - v;   // exclusive within tile + tile base
        ptr[i] = p;
        cur[i] = p;
    }
}

// --- scatter edges into both bin layouts; precompute rank scales for pass 2
__global__ void scatter_fill(const float* __restrict__ rank_masks,
                             const float* __restrict__ vals,
                             const void* __restrict__ he_idxs,
                             const void* __restrict__ rows,
                             const void* __restrict__ cols) {
    int is64 = g_is64;
    long long e = (long long)blockIdx.x * blockDim.x + threadIdx.x;
    if (e >= PNNZ) return;
    int row = (int)load_idx(rows, e, is64);
    int col = (int)load_idx(cols, e, is64);
    float v = vals[e];

    int p1 = atomicAdd(&g_cur_c[col], 1);
    g_e1[p1] = make_int2(row, __float_as_int(v));

    long long he = load_idx(he_idxs, col, is64);
    float s0 = rank_masks[(size_t)0 * PE + he] * v;
    float s1 = rank_masks[(size_t)1 * PE + he] * v;
    float s2 = rank_masks[(size_t)2 * PE + he] * v;
    int p2 = atomicAdd(&g_cur_r[row], 1);
    g_e2[p2] = make_float4(__int_as_float(col), s0, s1, s2);
}

// --- pass 1 (gather): he_feat[c, :] = sum over edges in col-bin c of x[row]*val
//     16 threads per hyperedge; each owns one float4 of the 64-float row.
__global__ void gather_edge_feat(const float4* __restrict__ x4) {
    long long g = ((long long)blockIdx.x * blockDim.x + threadIdx.x) >> 4;
    int sub = threadIdx.x & 15;
    if (g >= PE) return;
    int beg = g_ptr_c[g];
    int end = beg + g_cnt_c[g];
    float4 acc = make_float4(0.f, 0.f, 0.f, 0.f);
    #pragma unroll 4
    for (int i = beg; i < end; i++) {
        int2 eRec = g_e1[i];
        float v = __int_as_float(eRec.y);
        float4 a = x4[(long long)eRec.x * 16 + sub];
        acc.x += a.x * v; acc.y += a.y * v; acc.z += a.z * v; acc.w += a.w * v;
    }
    ((float4*)g_he_feat)[g * 16 + sub] = acc;   // dense, coalesced
}

// --- pass 2 (gather, fused with rank-3 init):
//     out[n, r, :] = sum over edges in row-bin n of s_r * he_feat[col, :] (r=0..2)
//     out[n, 3, :] = x[n, :]   -- full 1 KB node row written contiguously.
__global__ void gather_node_feat(float4* __restrict__ out4,
                                 const float4* __restrict__ x4) {
    long long n = ((long long)blockIdx.x * blockDim.x + threadIdx.x) >> 4;
    int sub = threadIdx.x & 15;
    if (n >= PN) return;
    int beg = g_ptr_r[n];
    int end = beg + g_cnt_r[n];
    const float4* hf4 = (const float4*)g_he_feat;
    float4 a0 = make_float4(0.f, 0.f, 0.f, 0.f);
    float4 a1 = a0, a2 = a0;
    #pragma unroll 4
    for (int i = beg; i < end; i++) {
        float4 m = g_e2[i];
        int col = __float_as_int(m.x);
        float4 h = hf4[(long long)col * 16 + sub];
        a0.x += h.x * m.y; a0.y += h.y * m.y; a0.z += h.z * m.y; a0.w += h.w * m.y;
        a1.x += h.x * m.z; a1.y += h.y * m.z; a1.z += h.z * m.z; a1.w += h.w * m.z;
        a2.x += h.x * m.w; a2.y += h.y * m.w; a2.z += h.z * m.w; a2.w += h.w * m.w;
    }
    float4* o = out4 + n * 64;          // 64 float4 per node row (R*F = 256 floats)
    o[sub]      = a0;
    o[16 + sub] = a1;
    o[32 + sub] = a2;
    o[48 + sub] = x4[n * 16 + sub];     // fused rank-3 = x
}

extern "C" void kernel_launch(void* const* d_in, const int* in_sizes, int n_in,
                              void* d_out, int out_size) {
    const float* x          = (const float*)d_in[0];   // (N, F)
    const float* rank_masks = (const float*)d_in[1];   // (R, E)
    const float* vals       = (const float*)d_in[2];   // (NNZ,)
    const void*  he_idxs    = d_in[3];                 // (E,)
    const void*  rows       = d_in[4];                 // (NNZ,)
    const void*  cols       = d_in[5];                 // (NNZ,)
    float4* out4 = (float4*)d_out;                     // (N, R, F)

    zero_and_detect<<<((PE + PN) + 255) / 256, 256>>>(rows);

    histogram_edges<<<(PNNZ / 4 + 255) / 256, 256>>>(rows, cols);

    assign_offsets<<<NB_C + NB_R, NTILE>>>();

    scatter_fill<<<(PNNZ + 255) / 256, 256>>>(rank_masks, vals, he_idxs, rows, cols);

    {
        long long threads = (long long)PE * 16;
        gather_edge_feat<<<(int)((threads + 255) / 256), 256>>>((const float4*)x);
    }
    {
        long long threads = (long long)PN * 16;
        gather_node_feat<<<(int)((threads + 255) / 256), 256>>>(out4, (const float4*)x);
    }
}

// round 10
// speedup vs baseline: 1.0679x; 1.0679x over previous
#include <cuda_runtime.h>
#include <cstdint>

// Problem constants (fixed shapes)
#define PN    100000   // nodes
#define PE    100000   // hyperedges
#define PNNZ  800000   // edges (nnz)
#define PR    4        // ranks
#define PF    64       // features

#define NTILE 1024
#define NB_C  ((PE + NTILE - 1) / NTILE)   // 98
#define NB_R  ((PN + NTILE - 1) / NTILE)   // 98

// ---- scratch (__device__ globals; no allocation). ~47 MB total.
// RULE (hard-won in rounds 3-6): these symbols are referenced ONLY from
// device code; never passed as host-side kernel arguments (host shadow
// address = UB = 128 MB checkpoint violation).
__device__ int    g_is64;
__device__ int    g_cnt_c[PE];
__device__ int    g_cnt_r[PN];
__device__ int    g_ptr_c[PE + 1];
__device__ int    g_ptr_r[PN + 1];
__device__ int    g_cur_c[PE];
__device__ int    g_cur_r[PN];
__device__ int    g_bsum[NB_C + NB_R];
__device__ __align__(16) float  g_he_feat[(size_t)PE * PF];   // 25.6 MB dense
__device__ __align__(8)  int2   g_e1[PNNZ];   // sorted by col: (row, val bits)      6.4 MB
__device__ __align__(16) float4 g_e2[PNNZ];   // sorted by row: (col bits, s0,s1,s2) 12.8 MB

__device__ __forceinline__ long long load_idx(const void* p, long long i, int is64) {
    if (is64) return ((const long long*)p)[i];
    return (long long)((const int*)p)[i];
}

// --- zero histograms + dtype sniff fused (every replay).
// int64 LE indices < 2^31 -> every odd 32-bit word is 0.
__global__ void zero_and_detect(const void* rows) {
    int t = blockIdx.x * blockDim.x + threadIdx.x;
    if (t == 0) {
        const int* p = (const int*)rows;
        int all0 = 1;
        #pragma unroll 4
        for (int i = 0; i < 1024; i++) {
            if (p[2 * i + 1] != 0) { all0 = 0; break; }
        }
        g_is64 = all0;
    }
    int total = PE + PN;
    for (; t < total; t += gridDim.x * blockDim.x) {
        if (t < PE) g_cnt_c[t] = 0;
        else        g_cnt_r[t - PE] = 0;
    }
}

// --- histogram edges by col and by row
__global__ void histogram_edges(const void* __restrict__ rows,
                                const void* __restrict__ cols) {
    int is64 = g_is64;
    long long e = (long long)blockIdx.x * blockDim.x + threadIdx.x;
    if (e >= PNNZ) return;
    int row = (int)load_idx(rows, e, is64);
    int col = (int)load_idx(cols, e, is64);
    atomicAdd(&g_cnt_c[col], 1);
    atomicAdd(&g_cnt_r[row], 1);
}

// ===================== multi-block exclusive scan =====================
// Phase 1: per-tile scan. Blocks [0, NB_C) handle g_cnt_c; [NB_C, NB_C+NB_R)
// handle g_cnt_r. Local exclusive prefix -> ptr; tile total -> g_bsum.
__global__ void scan_tiles() {
    __shared__ int sm[NTILE];
    int b = blockIdx.x;
    bool isC = (b < NB_C);
    const int* cnt = isC ? g_cnt_c : g_cnt_r;
    int*       ptr = isC ? g_ptr_c : g_ptr_r;
    int n    = isC ? PE : PN;
    int tile = isC ? b : b - NB_C;
    int t = threadIdx.x;
    int i = tile * NTILE + t;
    int v = (i < n) ? cnt[i] : 0;
    sm[t] = v;
    __syncthreads();
    #pragma unroll
    for (int d = 1; d < NTILE; d <<= 1) {
        int u = (t >= d) ? sm[t - d] : 0;
        __syncthreads();
        sm[t] += u;
        __syncthreads();
    }
    if (i < n) ptr[i] = sm[t] - v;          // local exclusive
    if (t == NTILE - 1) g_bsum[b] = sm[t];  // tile total
}

// Phase 2: scan the tile totals. One block; segment [0,128) = c tiles,
// segment [128,256) = r tiles, scanned independently.
__global__ void scan_bsums() {
    __shared__ int sm[256];
    int t = threadIdx.x;          // 0..255
    int seg = t >> 7;             // 0 = c, 1 = r
    int j = t & 127;
    int v = 0;
    if (seg == 0) { if (j < NB_C) v = g_bsum[j]; }
    else          { if (j < NB_R) v = g_bsum[NB_C + j]; }
    sm[t] = v;
    __syncthreads();
    #pragma unroll
    for (int d = 1; d < 128; d <<= 1) {
        int u = (j >= d) ? sm[t - d] : 0;
        __syncthreads();
        sm[t] += u;
        __syncthreads();
    }
    int excl = sm[t] - v;
    if (seg == 0) { if (j < NB_C) g_bsum[j] = excl; }
    else          { if (j < NB_R) g_bsum[NB_C + j] = excl; }
}

// Phase 3: add tile offsets; materialize cursors; set totals.
__global__ void add_offsets() {
    int t = blockIdx.x * blockDim.x + threadIdx.x;
    if (t == 0) { g_ptr_c[PE] = PNNZ; g_ptr_r[PN] = PNNZ; }
    int total = PE + PN;
    for (; t < total; t += gridDim.x * blockDim.x) {
        if (t < PE) {
            int p = g_ptr_c[t] + g_bsum[t / NTILE];
            g_ptr_c[t] = p;
            g_cur_c[t] = p;
        } else {
            int j = t - PE;
            int p = g_ptr_r[j] + g_bsum[NB_C + j / NTILE];
            g_ptr_r[j] = p;
            g_cur_r[j] = p;
        }
    }
}
// ======================================================================

// --- scatter edges into both sorted orders; 4 edges per thread with batched
// phases to hide the atomic-return L2 round trip (R9 profile: issue=5.8%,
// latency-bound). PNNZ % 4 == 0, so no remainder path.
__global__ void scatter_fill(const float* __restrict__ rank_masks,
                             const float* __restrict__ vals,
                             const void* __restrict__ he_idxs,
                             const void* __restrict__ rows,
                             const void* __restrict__ cols) {
    int is64 = g_is64;
    long long e0 = ((long long)blockIdx.x * blockDim.x + threadIdx.x) * 4;
    if (e0 >= PNNZ) return;

    // phase A: load 4 edges' indices + vals (vectorized)
    int r[4], c[4];
    if (is64) {
        const longlong2* r2 = (const longlong2*)rows;
        const longlong2* c2 = (const longlong2*)cols;
        longlong2 ra = r2[e0 >> 1], rb = r2[(e0 >> 1) + 1];
        longlong2 ca = c2[e0 >> 1], cb = c2[(e0 >> 1) + 1];
        r[0] = (int)ra.x; r[1] = (int)ra.y; r[2] = (int)rb.x; r[3] = (int)rb.y;
        c[0] = (int)ca.x; c[1] = (int)ca.y; c[2] = (int)cb.x; c[3] = (int)cb.y;
    } else {
        int4 ra = ((const int4*)rows)[e0 >> 2];
        int4 ca = ((const int4*)cols)[e0 >> 2];
        r[0] = ra.x; r[1] = ra.y; r[2] = ra.z; r[3] = ra.w;
        c[0] = ca.x; c[1] = ca.y; c[2] = ca.z; c[3] = ca.w;
    }
    float4 vv = ((const float4*)vals)[e0 >> 2];
    float v[4] = {vv.x, vv.y, vv.z, vv.w};

    // phase B: all 8 position atomics issued back-to-back (8 concurrent
    // L2 round trips per thread instead of 2 dependent ones per edge)
    int p1[4], p2[4];
    #pragma unroll
    for (int k = 0; k < 4; k++) p1[k] = atomicAdd(&g_cur_c[c[k]], 1);
    #pragma unroll
    for (int k = 0; k < 4; k++) p2[k] = atomicAdd(&g_cur_r[r[k]], 1);

    // phase C: he + rank-mask gathers (independent of the atomics)
    long long he[4];
    #pragma unroll
    for (int k = 0; k < 4; k++) he[k] = load_idx(he_idxs, c[k], is64);
    float s0[4], s1[4], s2[4];
    #pragma unroll
    for (int k = 0; k < 4; k++) {
        s0[k] = rank_masks[(size_t)0 * PE + he[k]] * v[k];
        s1[k] = rank_masks[(size_t)1 * PE + he[k]] * v[k];
        s2[k] = rank_masks[(size_t)2 * PE + he[k]] * v[k];
    }

    // phase D: stores
    #pragma unroll
    for (int k = 0; k < 4; k++)
        g_e1[p1[k]] = make_int2(r[k], __float_as_int(v[k]));
    #pragma unroll
    for (int k = 0; k < 4; k++)
        g_e2[p2[k]] = make_float4(__int_as_float(c[k]), s0[k], s1[k], s2[k]);
}

// --- pass 1 (gather): he_feat[c, :] = sum over edges in col-bin c of x[row]*val
//     16 threads per hyperedge; each owns one float4 of the 64-float row.
__global__ void gather_edge_feat(const float4* __restrict__ x4) {
    long long g = ((long long)blockIdx.x * blockDim.x + threadIdx.x) >> 4;
    int sub = threadIdx.x & 15;
    if (g >= PE) return;
    int beg = g_ptr_c[g];
    int end = g_ptr_c[g + 1];
    float4 acc = make_float4(0.f, 0.f, 0.f, 0.f);
    #pragma unroll 2
    for (int i = beg; i < end; i++) {
        int2 eRec = g_e1[i];
        float v = __int_as_float(eRec.y);
        float4 a = x4[(long long)eRec.x * 16 + sub];
        acc.x += a.x * v; acc.y += a.y * v; acc.z += a.z * v; acc.w += a.w * v;
    }
    ((float4*)g_he_feat)[g * 16 + sub] = acc;   // dense, coalesced
}

// --- pass 2 (gather, fused with rank-3 init):
//     out[n, r, :] = sum over edges in row-bin n of s_r * he_feat[col, :] (r=0..2)
//     out[n, 3, :] = x[n, :]   -- full 1 KB node row written contiguously.
__global__ void gather_node_feat(float4* __restrict__ out4,
                                 const float4* __restrict__ x4) {
    long long n = ((long long)blockIdx.x * blockDim.x + threadIdx.x) >> 4;
    int sub = threadIdx.x & 15;
    if (n >= PN) return;
    int beg = g_ptr_r[n];
    int end = g_ptr_r[n + 1];
    const float4* hf4 = (const float4*)g_he_feat;
    float4 a0 = make_float4(0.f, 0.f, 0.f, 0.f);
    float4 a1 = a0, a2 = a0;
    #pragma unroll 2
    for (int i = beg; i < end; i++) {
        float4 m = g_e2[i];
        int col = __float_as_int(m.x);
        float4 h = hf4[(long long)col * 16 + sub];
        a0.x += h.x * m.y; a0.y += h.y * m.y; a0.z += h.z * m.y; a0.w += h.w * m.y;
        a1.x += h.x * m.z; a1.y += h.y * m.z; a1.z += h.z * m.z; a1.w += h.w * m.z;
        a2.x += h.x * m.w; a2.y += h.y * m.w; a2.z += h.z * m.w; a2.w += h.w * m.w;
    }
    float4* o = out4 + n * 64;          // 64 float4 per node row (R*F = 256 floats)
    o[sub]      = a0;
    o[16 + sub] = a1;
    o[32 + sub] = a2;
    o[48 + sub] = x4[n * 16 + sub];     // fused rank-3 = x
}

extern "C" void kernel_launch(void* const* d_in, const int* in_sizes, int n_in,
                              void* d_out, int out_size) {
    const float* x          = (const float*)d_in[0];   // (N, F)
    const float* rank_masks = (const float*)d_in[1];   // (R, E)
    const float* vals       = (const float*)d_in[2];   // (NNZ,)
    const void*  he_idxs    = d_in[3];                 // (E,)
    const void*  rows       = d_in[4];                 // (NNZ,)
    const void*  cols       = d_in[5];                 // (NNZ,)
    float4* out4 = (float4*)d_out;                     // (N, R, F)

    zero_and_detect<<<((PE + PN) + 255) / 256, 256>>>(rows);

    histogram_edges<<<(PNNZ + 255) / 256, 256>>>(rows, cols);

    scan_tiles<<<NB_C + NB_R, NTILE>>>();
    scan_bsums<<<1, 256>>>();
    add_offsets<<<((PE + PN) + 255) / 256, 256>>>();

    scatter_fill<<<(PNNZ / 4 + 255) / 256, 256>>>(rank_masks, vals, he_idxs, rows, cols);

    {
        long long threads = (long long)PE * 16;
        gather_edge_feat<<<(int)((threads + 255) / 256), 256>>>((const float4*)x);
    }
    {
        long long threads = (long long)PN * 16;
        gather_node_feat<<<(int)((threads + 255) / 256), 256>>>(out4, (const float4*)x);
    }
}

// round 11
// speedup vs baseline: 1.1598x; 1.0861x over previous
#include <cuda_runtime.h>
#include <cstdint>

// Problem constants (fixed shapes)
#define PN    100000   // nodes
#define PE    100000   // hyperedges
#define PNNZ  800000   // edges (nnz)
#define PR    4        // ranks
#define PF    64       // features

#define NTILE 1024
#define NB_C  ((PE + NTILE - 1) / NTILE)   // 98
#define NB_R  ((PN + NTILE - 1) / NTILE)   // 98

// ---- scratch (__device__ globals; no allocation). ~42 MB total.
// RULE (hard-won in rounds 3-6): these symbols are referenced ONLY from
// device code; never passed as host-side kernel arguments (host shadow
// address = UB = 128 MB checkpoint violation).
__device__ int    g_is64;
__device__ int    g_cnt_c[PE];
__device__ int    g_cnt_r[PN];
__device__ int    g_ptr_c[PE + 1];
__device__ int    g_ptr_r[PN + 1];
__device__ int    g_cur_c[PE];
__device__ int    g_cur_r[PN];
__device__ int    g_bsum[NB_C + NB_R];
__device__ __align__(16) float4 g_scales[PE];                 // (rm0,rm1,rm2,_)[he_idxs[c]]  1.6 MB
__device__ __align__(16) float  g_he_feat[(size_t)PE * PF];   // 25.6 MB dense
__device__ __align__(8)  int2   g_e1[PNNZ];   // by col: (row, val bits)   6.4 MB
__device__ __align__(8)  int2   g_e2[PNNZ];   // by row: (col, val bits)   6.4 MB

__device__ __forceinline__ long long load_idx(const void* p, long long i, int is64) {
    if (is64) return ((const long long*)p)[i];
    return (long long)((const int*)p)[i];
}

// --- zero histograms + dtype sniff fused (every replay).
// int64 LE indices < 2^31 -> every odd 32-bit word is 0.
__global__ void zero_and_detect(const void* rows) {
    int t = blockIdx.x * blockDim.x + threadIdx.x;
    if (t == 0) {
        const int* p = (const int*)rows;
        int all0 = 1;
        #pragma unroll 4
        for (int i = 0; i < 1024; i++) {
            if (p[2 * i + 1] != 0) { all0 = 0; break; }
        }
        g_is64 = all0;
    }
    int total = PE + PN;
    for (; t < total; t += gridDim.x * blockDim.x) {
        if (t < PE) g_cnt_c[t] = 0;
        else        g_cnt_r[t - PE] = 0;
    }
}

// --- histogram edges by col and by row; fused per-hyperedge scale precompute
//     (threads e < PE also build g_scales[e] = rank_masks[0..2, he_idxs[e]])
__global__ void histogram_edges(const void* __restrict__ rows,
                                const void* __restrict__ cols,
                                const void* __restrict__ he_idxs,
                                const float* __restrict__ rank_masks) {
    int is64 = g_is64;
    long long e = (long long)blockIdx.x * blockDim.x + threadIdx.x;
    if (e >= PNNZ) return;
    int row = (int)load_idx(rows, e, is64);
    int col = (int)load_idx(cols, e, is64);
    atomicAdd(&g_cnt_c[col], 1);
    atomicAdd(&g_cnt_r[row], 1);
    if (e < PE) {
        long long he = load_idx(he_idxs, e, is64);
        g_scales[e] = make_float4(rank_masks[he],
                                  rank_masks[(size_t)PE + he],
                                  rank_masks[(size_t)2 * PE + he],
                                  0.0f);
    }
}

// ===================== multi-block exclusive scan =====================
// Phase 1: per-tile scan. Blocks [0, NB_C) handle g_cnt_c; [NB_C, NB_C+NB_R)
// handle g_cnt_r. Local exclusive prefix -> ptr; tile total -> g_bsum.
__global__ void scan_tiles() {
    __shared__ int sm[NTILE];
    int b = blockIdx.x;
    bool isC = (b < NB_C);
    const int* cnt = isC ? g_cnt_c : g_cnt_r;
    int*       ptr = isC ? g_ptr_c : g_ptr_r;
    int n    = isC ? PE : PN;
    int tile = isC ? b : b - NB_C;
    int t = threadIdx.x;
    int i = tile * NTILE + t;
    int v = (i < n) ? cnt[i] : 0;
    sm[t] = v;
    __syncthreads();
    #pragma unroll
    for (int d = 1; d < NTILE; d <<= 1) {
        int u = (t >= d) ? sm[t - d] : 0;
        __syncthreads();
        sm[t] += u;
        __syncthreads();
    }
    if (i < n) ptr[i] = sm[t] - v;          // local exclusive
    if (t == NTILE - 1) g_bsum[b] = sm[t];  // tile total
}

// Phase 2: scan the tile totals. One block; segment [0,128) = c tiles,
// segment [128,256) = r tiles, scanned independently.
__global__ void scan_bsums() {
    __shared__ int sm[256];
    int t = threadIdx.x;          // 0..255
    int seg = t >> 7;             // 0 = c, 1 = r
    int j = t & 127;
    int v = 0;
    if (seg == 0) { if (j < NB_C) v = g_bsum[j]; }
    else          { if (j < NB_R) v = g_bsum[NB_C + j]; }
    sm[t] = v;
    __syncthreads();
    #pragma unroll
    for (int d = 1; d < 128; d <<= 1) {
        int u = (j >= d) ? sm[t - d] : 0;
        __syncthreads();
        sm[t] += u;
        __syncthreads();
    }
    int excl = sm[t] - v;
    if (seg == 0) { if (j < NB_C) g_bsum[j] = excl; }
    else          { if (j < NB_R) g_bsum[NB_C + j] = excl; }
}

// Phase 3: add tile offsets; materialize cursors; set totals.
__global__ void add_offsets() {
    int t = blockIdx.x * blockDim.x + threadIdx.x;
    if (t == 0) { g_ptr_c[PE] = PNNZ; g_ptr_r[PN] = PNNZ; }
    int total = PE + PN;
    for (; t < total; t += gridDim.x * blockDim.x) {
        if (t < PE) {
            int p = g_ptr_c[t] + g_bsum[t / NTILE];
            g_ptr_c[t] = p;
            g_cur_c[t] = p;
        } else {
            int j = t - PE;
            int p = g_ptr_r[j] + g_bsum[NB_C + j / NTILE];
            g_ptr_r[j] = p;
            g_cur_r[j] = p;
        }
    }
}
// ======================================================================

// --- scatter edges into both sorted orders (one edge per thread — R10's
//     intra-thread batching regressed; cross-warp MLP wins for scattered
//     atomics). Rank scales now live in g_scales, so records are 8 B each.
__global__ void scatter_fill(const float* __restrict__ vals,
                             const void* __restrict__ rows,
                             const void* __restrict__ cols) {
    int is64 = g_is64;
    long long e = (long long)blockIdx.x * blockDim.x + threadIdx.x;
    if (e >= PNNZ) return;
    int row = (int)load_idx(rows, e, is64);
    int col = (int)load_idx(cols, e, is64);
    int vbits = __float_as_int(vals[e]);

    int p1 = atomicAdd(&g_cur_c[col], 1);
    g_e1[p1] = make_int2(row, vbits);

    int p2 = atomicAdd(&g_cur_r[row], 1);
    g_e2[p2] = make_int2(col, vbits);
}

// --- pass 1 (gather): he_feat[c, :] = sum over edges in col-bin c of x[row]*val
//     16 threads per hyperedge; each owns one float4 of the 64-float row.
__global__ void gather_edge_feat(const float4* __restrict__ x4) {
    long long g = ((long long)blockIdx.x * blockDim.x + threadIdx.x) >> 4;
    int sub = threadIdx.x & 15;
    if (g >= PE) return;
    int beg = g_ptr_c[g];
    int end = g_ptr_c[g + 1];
    float4 acc = make_float4(0.f, 0.f, 0.f, 0.f);
    #pragma unroll 2
    for (int i = beg; i < end; i++) {
        int2 eRec = g_e1[i];
        float v = __int_as_float(eRec.y);
        float4 a = x4[(long long)eRec.x * 16 + sub];
        acc.x += a.x * v; acc.y += a.y * v; acc.z += a.z * v; acc.w += a.w * v;
    }
    ((float4*)g_he_feat)[g * 16 + sub] = acc;   // dense, coalesced
}

// --- pass 2 (gather, fused with rank-3 init):
//     out[n, r, :] = sum over edges in row-bin n of
//         (g_scales[col].r * val) * he_feat[col, :]   (r = 0..2)
//     out[n, 3, :] = x[n, :]   -- full 1 KB node row written contiguously.
__global__ void gather_node_feat(float4* __restrict__ out4,
                                 const float4* __restrict__ x4) {
    long long n = ((long long)blockIdx.x * blockDim.x + threadIdx.x) >> 4;
    int sub = threadIdx.x & 15;
    if (n >= PN) return;
    int beg = g_ptr_r[n];
    int end = g_ptr_r[n + 1];
    const float4* hf4 = (const float4*)g_he_feat;
    float4 a0 = make_float4(0.f, 0.f, 0.f, 0.f);
    float4 a1 = a0, a2 = a0;
    #pragma unroll 2
    for (int i = beg; i < end; i++) {
        int2 m = g_e2[i];
        int col = m.x;
        float v = __int_as_float(m.y);
        float4 sc = g_scales[col];          // broadcast across the 16 lanes; L2-hot
        float4 h  = hf4[(long long)col * 16 + sub];
        float s0 = sc.x * v, s1 = sc.y * v, s2 = sc.z * v;
        a0.x += h.x * s0; a0.y += h.y * s0; a0.z += h.z * s0; a0.w += h.w * s0;
        a1.x += h.x * s1; a1.y += h.y * s1; a1.z += h.z * s1; a1.w += h.w * s1;
        a2.x += h.x * s2; a2.y += h.y * s2; a2.z += h.z * s2; a2.w += h.w * s2;
    }
    float4* o = out4 + n * 64;          // 64 float4 per node row (R*F = 256 floats)
    o[sub]      = a0;
    o[16 + sub] = a1;
    o[32 + sub] = a2;
    o[48 + sub] = x4[n * 16 + sub];     // fused rank-3 = x
}

extern "C" void kernel_launch(void* const* d_in, const int* in_sizes, int n_in,
                              void* d_out, int out_size) {
    const float* x          = (const float*)d_in[0];   // (N, F)
    const float* rank_masks = (const float*)d_in[1];   // (R, E)
    const float* vals       = (const float*)d_in[2];   // (NNZ,)
    const void*  he_idxs    = d_in[3];                 // (E,)
    const void*  rows       = d_in[4];                 // (NNZ,)
    const void*  cols       = d_in[5];                 // (NNZ,)
    float4* out4 = (float4*)d_out;                     // (N, R, F)

    zero_and_detect<<<((PE + PN) + 255) / 256, 256>>>(rows);

    histogram_edges<<<(PNNZ + 255) / 256, 256>>>(rows, cols, he_idxs, rank_masks);

    scan_tiles<<<NB_C + NB_R, NTILE>>>();
    scan_bsums<<<1, 256>>>();
    add_offsets<<<((PE + PN) + 255) / 256, 256>>>();

    scatter_fill<<<(PNNZ + 255) / 256, 256>>>(vals, rows, cols);

    {
        long long threads = (long long)PE * 16;
        gather_edge_feat<<<(int)((threads + 255) / 256), 256>>>((const float4*)x);
    }
    {
        long long threads = (long long)PN * 16;
        gather_node_feat<<<(int)((threads + 255) / 256), 256>>>(out4, (const float4*)x);
    }
}